// round 2
// baseline (speedup 1.0000x reference)
#include <cuda_runtime.h>
#include <cuda_bf16.h>

#define N_NODES 100000
#define N_EDGES 1600000
#define COUT 64
#define CIN 128

// ---------------- scratch (no allocations allowed) ----------------
__device__ float g_deg[N_NODES];
__device__ float g_dinv[N_NODES];
__device__ float g_xs[(size_t)N_NODES * COUT];   // xw * dinv[row], gather source
__device__ float g_sums[COUT];
__device__ float g_sumsq[COUT];
__device__ float g_A[COUT];
__device__ float g_B[COUT];

// ---------------- 1. init deg=1 (self loop), zero BN accumulators ----------------
__global__ void k_init() {
    int i = blockIdx.x * blockDim.x + threadIdx.x;
    if (i < N_NODES) g_deg[i] = 1.0f;
    if (i < COUT) { g_sums[i] = 0.0f; g_sumsq[i] = 0.0f; }
}

// ---------------- 2. degree count over targets (col) ----------------
__global__ void k_deg(const int* __restrict__ col) {
    int e = blockIdx.x * blockDim.x + threadIdx.x;
    if (e < N_EDGES) atomicAdd(&g_deg[col[e]], 1.0f);
}

// ---------------- 3. dinv = rsqrt(deg) ----------------
__global__ void k_dinv() {
    int i = blockIdx.x * blockDim.x + threadIdx.x;
    if (i < N_NODES) g_dinv[i] = rsqrtf(g_deg[i]);
}

// ---------------- 4. xs = (x @ W) * dinv[row]; agg init = xs (self loop) ----------
// 64-row tile per block, 256 threads, each thread computes 4x4 outputs.
// W (128x64) and transposed x tile (128 x 68 padded) in dynamic smem.
__global__ void __launch_bounds__(256) k_gemm(const float* __restrict__ x,
                                              const float* __restrict__ W,
                                              float* __restrict__ agg) {
    extern __shared__ float smem[];
    float* sW = smem;              // 8192 floats
    float* sX = smem + 8192;       // 128 * 68 floats (transposed, padded)
    const int tid = threadIdx.x;
    const int base = blockIdx.x * 64;

    // load W (128x64) as float4
    {
        const float4* W4 = (const float4*)W;
        float4* sW4 = (float4*)sW;
        #pragma unroll
        for (int i = tid; i < 2048; i += 256) sW4[i] = W4[i];
    }
    // load x tile [64][128] -> transposed sX[k][r], pad 68
    {
        const float4* x4 = (const float4*)x;
        #pragma unroll
        for (int i = tid; i < 2048; i += 256) {
            int r = i >> 5;          // 0..63
            int kq = i & 31;         // float4 idx within row
            int row = base + r;
            float4 v = make_float4(0.f, 0.f, 0.f, 0.f);
            if (row < N_NODES) v = x4[row * 32 + kq];
            int k = kq << 2;
            sX[(k + 0) * 68 + r] = v.x;
            sX[(k + 1) * 68 + r] = v.y;
            sX[(k + 2) * 68 + r] = v.z;
            sX[(k + 3) * 68 + r] = v.w;
        }
    }
    __syncthreads();

    const int c0 = (tid & 15) * 4;   // output cols
    const int r0 = (tid >> 4) * 4;   // output rows within tile
    float acc[4][4] = {};

    #pragma unroll 4
    for (int k = 0; k < 128; k++) {
        float4 wv = *(const float4*)&sW[k * 64 + c0];
        float4 xv = *(const float4*)&sX[k * 68 + r0];
        float xr[4] = {xv.x, xv.y, xv.z, xv.w};
        float wr[4] = {wv.x, wv.y, wv.z, wv.w};
        #pragma unroll
        for (int j = 0; j < 4; j++)
            #pragma unroll
            for (int i2 = 0; i2 < 4; i2++)
                acc[j][i2] += xr[j] * wr[i2];
    }

    #pragma unroll
    for (int j = 0; j < 4; j++) {
        int row = base + r0 + j;
        if (row < N_NODES) {
            float di = g_dinv[row];
            float4 v = make_float4(acc[j][0] * di, acc[j][1] * di,
                                   acc[j][2] * di, acc[j][3] * di);
            ((float4*)g_xs)[row * 16 + (c0 >> 2)] = v;
            ((float4*)agg)[row * 16 + (c0 >> 2)] = v;   // self-loop init
        }
    }
}

// ---------------- 5. edge scatter: agg[col] += xs[row] (vec4 RED) ----------------
// 16 threads per edge, each moves one float4.
__global__ void __launch_bounds__(256) k_scatter(const int* __restrict__ rowIdx,
                                                 const int* __restrict__ colIdx,
                                                 float* __restrict__ agg) {
    int gid = blockIdx.x * 256 + threadIdx.x;
    int e = gid >> 4;
    if (e >= N_EDGES) return;
    int comp = gid & 15;
    int r = rowIdx[e];
    int c = colIdx[e];
    float4 v = ((const float4*)g_xs)[r * 16 + comp];
    float* dst = agg + (size_t)c * 64 + comp * 4;
    asm volatile("red.global.add.v4.f32 [%0], {%1,%2,%3,%4};"
                 :: "l"(dst), "f"(v.x), "f"(v.y), "f"(v.z), "f"(v.w)
                 : "memory");
}

// ---------------- 6. BN stats: per-channel sum / sumsq of o = dinv*agg + b ------
__global__ void __launch_bounds__(256) k_stats(const float* __restrict__ agg,
                                               const float* __restrict__ b) {
    __shared__ float s1[COUT], s2[COUT];
    int tid = threadIdx.x;
    if (tid < COUT) { s1[tid] = 0.f; s2[tid] = 0.f; }
    __syncthreads();
    const int stride = gridDim.x * 256;
    int idx0 = blockIdx.x * 256 + tid;
    int c = idx0 & 63;               // constant per thread (stride % 64 == 0)
    float bc = b[c];
    float sum = 0.f, sq = 0.f;
    for (int idx = idx0; idx < N_NODES * 64; idx += stride) {
        int i = idx >> 6;
        float o = g_dinv[i] * agg[idx] + bc;
        sum += o;
        sq += o * o;
    }
    atomicAdd(&s1[c], sum);
    atomicAdd(&s2[c], sq);
    __syncthreads();
    if (tid < COUT) {
        atomicAdd(&g_sums[tid], s1[tid]);
        atomicAdd(&g_sumsq[tid], s2[tid]);
    }
}

// ---------------- 7. fold BN into per-channel affine A, B ----------------
__global__ void k_fold(const float* __restrict__ b,
                       const float* __restrict__ gamma,
                       const float* __restrict__ beta) {
    int c = threadIdx.x;
    if (c < COUT) {
        float inv_n = 1.0f / (float)N_NODES;
        float mean = g_sums[c] * inv_n;
        float var = g_sumsq[c] * inv_n - mean * mean;
        float scale = gamma[c] * rsqrtf(var + 1e-5f);
        g_A[c] = scale;
        g_B[c] = scale * (b[c] - mean) + beta[c];
    }
}

// ---------------- 8. final: y = leaky(A*(dinv*agg) + B), in place ----------------
__global__ void __launch_bounds__(256) k_final(float* __restrict__ out) {
    int q = blockIdx.x * 256 + threadIdx.x;      // float4 index
    if (q >= N_NODES * 16) return;
    int i = q >> 4;
    int cq = q & 15;
    float di = g_dinv[i];
    float4 a = ((const float4*)g_A)[cq];
    float4 bb = ((const float4*)g_B)[cq];
    float4 v = ((float4*)out)[q];
    float4 y;
    y.x = a.x * (di * v.x) + bb.x;
    y.y = a.y * (di * v.y) + bb.y;
    y.z = a.z * (di * v.z) + bb.z;
    y.w = a.w * (di * v.w) + bb.w;
    y.x = (y.x >= 0.f) ? y.x : 0.01f * y.x;
    y.y = (y.y >= 0.f) ? y.y : 0.01f * y.y;
    y.z = (y.z >= 0.f) ? y.z : 0.01f * y.z;
    y.w = (y.w >= 0.f) ? y.w : 0.01f * y.w;
    ((float4*)out)[q] = y;
}

extern "C" void kernel_launch(void* const* d_in, const int* in_sizes, int n_in,
                              void* d_out, int out_size) {
    const float* x      = (const float*)d_in[0];
    const int*   eidx   = (const int*)d_in[1];     // [2, E]: row then col
    const float* W      = (const float*)d_in[2];
    const float* b      = (const float*)d_in[3];
    const float* gamma  = (const float*)d_in[4];
    const float* beta   = (const float*)d_in[5];
    float* out = (float*)d_out;

    const int* rowIdx = eidx;
    const int* colIdx = eidx + N_EDGES;

    static bool attr_set = false;
    const int gemm_smem = (8192 + 128 * 68) * sizeof(float);   // 67584 B
    if (!attr_set) {
        cudaFuncSetAttribute(k_gemm, cudaFuncAttributeMaxDynamicSharedMemorySize, gemm_smem);
        attr_set = true;
    }

    k_init<<<(N_NODES + 255) / 256, 256>>>();
    k_deg<<<(N_EDGES + 255) / 256, 256>>>(colIdx);
    k_dinv<<<(N_NODES + 255) / 256, 256>>>();
    k_gemm<<<(N_NODES + 63) / 64, 256, gemm_smem>>>(x, W, out);
    k_scatter<<<(N_EDGES * 16) / 256, 256>>>(rowIdx, colIdx, out);
    k_stats<<<2048, 256>>>(out, b);
    k_fold<<<1, 64>>>(b, gamma, beta);
    k_final<<<(N_NODES * 16 + 255) / 256, 256>>>(out);
}

// round 3
// speedup vs baseline: 1.4279x; 1.4279x over previous
#include <cuda_runtime.h>
#include <cuda_bf16.h>

#define N_NODES 100000
#define N_EDGES 1600000
#define COUT 64
#define CIN 128
#define NBLK_SCAN 391   // ceil(100000/256)

// ---------------- scratch (no allocations allowed) ----------------
__device__ float g_deg[N_NODES];
__device__ float g_dinv[N_NODES];
__device__ float g_xs[(size_t)N_NODES * COUT];   // xw * dinv[row], gather source
__device__ int   g_off[N_NODES];                 // CSR offsets (by target)
__device__ int   g_cnt[N_NODES];                 // fill counters -> edge in-degree
__device__ int   g_srow[N_EDGES];                // CSR-sorted source row ids
__device__ int   g_bsum[512];
__device__ int   g_bscan[512];
__device__ float g_sums[COUT];
__device__ float g_sumsq[COUT];
__device__ float g_A[COUT];
__device__ float g_B[COUT];

// packed f32x2 helpers
__device__ __forceinline__ unsigned long long pack_dup(float x) {
    unsigned long long p;
    unsigned u = __float_as_uint(x);
    asm("mov.b64 %0, {%1, %1};" : "=l"(p) : "r"(u));
    return p;
}
__device__ __forceinline__ void ffma2(unsigned long long& d,
                                      unsigned long long a,
                                      unsigned long long b) {
    asm("fma.rn.f32x2 %0, %1, %2, %3;" : "=l"(d) : "l"(a), "l"(b), "l"(d));
}
__device__ __forceinline__ void unpack2(unsigned long long p, float& lo, float& hi) {
    unsigned a, b2;
    asm("mov.b64 {%0, %1}, %2;" : "=r"(a), "=r"(b2) : "l"(p));
    lo = __uint_as_float(a);
    hi = __uint_as_float(b2);
}

// ---------------- 1. init ----------------
__global__ void k_init() {
    int i = blockIdx.x * blockDim.x + threadIdx.x;
    if (i < N_NODES) { g_deg[i] = 1.0f; g_cnt[i] = 0; }
    if (i < COUT) { g_sums[i] = 0.0f; g_sumsq[i] = 0.0f; }
}

// ---------------- 2. degree count over targets ----------------
__global__ void k_deg(const int* __restrict__ col) {
    int e = blockIdx.x * blockDim.x + threadIdx.x;
    if (e < N_EDGES) atomicAdd(&g_deg[col[e]], 1.0f);
}

// ---------------- 3. dinv = rsqrt(deg) ----------------
__global__ void k_dinv() {
    int i = blockIdx.x * blockDim.x + threadIdx.x;
    if (i < N_NODES) g_dinv[i] = rsqrtf(g_deg[i]);
}

// ---------------- 4a. per-block exclusive scan of edge in-degree --------------
__global__ void k_blockscan() {
    __shared__ int s[256];
    int tid = threadIdx.x;
    int i = blockIdx.x * 256 + tid;
    int v = 0;
    if (i < N_NODES) v = (int)g_deg[i] - 1;   // exclude self loop
    s[tid] = v;
    __syncthreads();
    #pragma unroll
    for (int d = 1; d < 256; d <<= 1) {
        int t = (tid >= d) ? s[tid - d] : 0;
        __syncthreads();
        s[tid] += t;
        __syncthreads();
    }
    if (i < N_NODES) g_off[i] = s[tid] - v;
    if (tid == 255) g_bsum[blockIdx.x] = s[255];
}

// ---------------- 4b. scan block sums (single block, 512 wide) ----------------
__global__ void k_scanb() {
    __shared__ int s[512];
    int tid = threadIdx.x;
    int v = (tid < NBLK_SCAN) ? g_bsum[tid] : 0;
    s[tid] = v;
    __syncthreads();
    #pragma unroll
    for (int d = 1; d < 512; d <<= 1) {
        int t = (tid >= d) ? s[tid - d] : 0;
        __syncthreads();
        s[tid] += t;
        __syncthreads();
    }
    g_bscan[tid] = s[tid] - v;   // exclusive
}

// ---------------- 4c. add block offsets ----------------
__global__ void k_offadd() {
    int i = blockIdx.x * 256 + threadIdx.x;
    if (i < N_NODES) g_off[i] += g_bscan[i >> 8];
}

// ---------------- 5. bin edges into CSR (by target) ----------------
__global__ void k_bin(const int* __restrict__ rowIdx, const int* __restrict__ colIdx) {
    int e = blockIdx.x * blockDim.x + threadIdx.x;
    if (e < N_EDGES) {
        int c = colIdx[e];
        int p = atomicAdd(&g_cnt[c], 1);
        g_srow[g_off[c] + p] = rowIdx[e];
    }
}

// ---------------- 6. GEMM: xs = (x @ W) * dinv[row] --------------------------
// 256-row x 64-col tile, 256 threads, 8x8 per thread, packed f32x2 FFMA.
// smem: W[128][64] resident + x chunk transposed [32][260 pad], 4 chunks.
#define XPAD 260
__global__ void __launch_bounds__(256, 2) k_gemm(const float* __restrict__ x,
                                                 const float* __restrict__ W) {
    extern __shared__ float smem[];
    float* sW = smem;              // 8192 floats
    float* sX = smem + 8192;       // 32 * 260 floats
    const int tid = threadIdx.x;
    const int base = blockIdx.x * 256;

    // load W (128x64) as float4
    {
        const float4* W4 = (const float4*)W;
        float4* sW4 = (float4*)sW;
        #pragma unroll
        for (int i = tid; i < 2048; i += 256) sW4[i] = W4[i];
    }

    const int c0 = (tid & 7) * 8;    // output cols  (0..56)
    const int r0 = (tid >> 3) * 8;   // output rows within tile (0..248)

    unsigned long long acc[8][4];
    #pragma unroll
    for (int j = 0; j < 8; j++)
        #pragma unroll
        for (int p = 0; p < 4; p++) acc[j][p] = 0ULL;

    const float4* x4 = (const float4*)x;

    for (int cc = 0; cc < 4; cc++) {
        const int k0 = cc * 32;
        __syncthreads();
        // stage x[base .. base+255][k0 .. k0+31] transposed into sX[k][r]
        #pragma unroll
        for (int t = 0; t < 8; t++) {
            int idx = tid + t * 256;          // 0..2047
            int r = idx >> 3;                 // 0..255
            int kq = idx & 7;                 // float4 within 32-k chunk
            int row = base + r;
            float4 v = make_float4(0.f, 0.f, 0.f, 0.f);
            if (row < N_NODES) v = x4[row * 32 + (k0 >> 2) + kq];
            int kl = kq << 2;
            sX[(kl + 0) * XPAD + r] = v.x;
            sX[(kl + 1) * XPAD + r] = v.y;
            sX[(kl + 2) * XPAD + r] = v.z;
            sX[(kl + 3) * XPAD + r] = v.w;
        }
        __syncthreads();

        #pragma unroll 4
        for (int kk = 0; kk < 32; kk++) {
            const int k = k0 + kk;
            // 8 cols of W as 4 packed pairs
            ulonglong2 wp0 = *(const ulonglong2*)&sW[k * 64 + c0];
            ulonglong2 wp1 = *(const ulonglong2*)&sW[k * 64 + c0 + 4];
            unsigned long long wv[4] = {wp0.x, wp0.y, wp1.x, wp1.y};
            // 8 rows of x, duplicated into pairs
            float4 xv0 = *(const float4*)&sX[kk * XPAD + r0];
            float4 xv1 = *(const float4*)&sX[kk * XPAD + r0 + 4];
            float xr[8] = {xv0.x, xv0.y, xv0.z, xv0.w, xv1.x, xv1.y, xv1.z, xv1.w};
            #pragma unroll
            for (int j = 0; j < 8; j++) {
                unsigned long long xd = pack_dup(xr[j]);
                #pragma unroll
                for (int p = 0; p < 4; p++) ffma2(acc[j][p], xd, wv[p]);
            }
        }
    }

    // epilogue: scale by dinv[row], store xs
    #pragma unroll
    for (int j = 0; j < 8; j++) {
        int row = base + r0 + j;
        if (row < N_NODES) {
            float di = g_dinv[row];
            float o[8];
            #pragma unroll
            for (int p = 0; p < 4; p++) unpack2(acc[j][p], o[2 * p], o[2 * p + 1]);
            float4 v0 = make_float4(o[0] * di, o[1] * di, o[2] * di, o[3] * di);
            float4 v1 = make_float4(o[4] * di, o[5] * di, o[6] * di, o[7] * di);
            ((float4*)g_xs)[row * 16 + (c0 >> 2)] = v0;
            ((float4*)g_xs)[row * 16 + (c0 >> 2) + 1] = v1;
        }
    }
}

// ---------------- 7. CSR gather-aggregate: out = dinv*(xs[self] + sum xs[src]) -
// 16 threads per node, each owns one float4 channel group. No atomics.
__global__ void __launch_bounds__(256) k_agg(float* __restrict__ out) {
    int gid = blockIdx.x * 256 + threadIdx.x;
    if (gid >= N_NODES * 16) return;
    int node = gid >> 4;
    int comp = gid & 15;
    const float4* xs4 = (const float4*)g_xs;

    float4 acc = xs4[node * 16 + comp];   // self loop
    int beg = g_off[node];
    int end = beg + g_cnt[node];
    int j = beg;
    for (; j + 4 <= end; j += 4) {
        int r0 = g_srow[j], r1 = g_srow[j + 1], r2 = g_srow[j + 2], r3 = g_srow[j + 3];
        float4 a = xs4[r0 * 16 + comp];
        float4 b = xs4[r1 * 16 + comp];
        float4 c = xs4[r2 * 16 + comp];
        float4 d = xs4[r3 * 16 + comp];
        acc.x += (a.x + b.x) + (c.x + d.x);
        acc.y += (a.y + b.y) + (c.y + d.y);
        acc.z += (a.z + b.z) + (c.z + d.z);
        acc.w += (a.w + b.w) + (c.w + d.w);
    }
    for (; j < end; j++) {
        float4 a = xs4[g_srow[j] * 16 + comp];
        acc.x += a.x; acc.y += a.y; acc.z += a.z; acc.w += a.w;
    }
    float di = g_dinv[node];
    acc.x *= di; acc.y *= di; acc.z *= di; acc.w *= di;
    ((float4*)out)[gid] = acc;
}

// ---------------- 8. BN stats on o = v + b ----------------
__global__ void __launch_bounds__(256) k_stats(const float* __restrict__ v,
                                               const float* __restrict__ b) {
    __shared__ float s1[COUT], s2[COUT];
    int tid = threadIdx.x;
    if (tid < COUT) { s1[tid] = 0.f; s2[tid] = 0.f; }
    __syncthreads();
    const int stride = gridDim.x * 256;
    int idx0 = blockIdx.x * 256 + tid;
    int c = idx0 & 63;
    float bc = b[c];
    float sum = 0.f, sq = 0.f;
    for (int idx = idx0; idx < N_NODES * 64; idx += stride) {
        float o = v[idx] + bc;
        sum += o;
        sq += o * o;
    }
    atomicAdd(&s1[c], sum);
    atomicAdd(&s2[c], sq);
    __syncthreads();
    if (tid < COUT) {
        atomicAdd(&g_sums[tid], s1[tid]);
        atomicAdd(&g_sumsq[tid], s2[tid]);
    }
}

// ---------------- 9. fold BN into per-channel affine ----------------
__global__ void k_fold(const float* __restrict__ b,
                       const float* __restrict__ gamma,
                       const float* __restrict__ beta) {
    int c = threadIdx.x;
    if (c < COUT) {
        float inv_n = 1.0f / (float)N_NODES;
        float mean = g_sums[c] * inv_n;
        float var = g_sumsq[c] * inv_n - mean * mean;
        float scale = gamma[c] * rsqrtf(var + 1e-5f);
        g_A[c] = scale;
        g_B[c] = scale * (b[c] - mean) + beta[c];
    }
}

// ---------------- 10. final: y = leaky(A*v + B), in place ----------------
__global__ void __launch_bounds__(256) k_final(float* __restrict__ out) {
    int q = blockIdx.x * 256 + threadIdx.x;
    if (q >= N_NODES * 16) return;
    int cq = q & 15;
    float4 a = ((const float4*)g_A)[cq];
    float4 bb = ((const float4*)g_B)[cq];
    float4 v = ((float4*)out)[q];
    float4 y;
    y.x = a.x * v.x + bb.x;
    y.y = a.y * v.y + bb.y;
    y.z = a.z * v.z + bb.z;
    y.w = a.w * v.w + bb.w;
    y.x = (y.x >= 0.f) ? y.x : 0.01f * y.x;
    y.y = (y.y >= 0.f) ? y.y : 0.01f * y.y;
    y.z = (y.z >= 0.f) ? y.z : 0.01f * y.z;
    y.w = (y.w >= 0.f) ? y.w : 0.01f * y.w;
    ((float4*)out)[q] = y;
}

extern "C" void kernel_launch(void* const* d_in, const int* in_sizes, int n_in,
                              void* d_out, int out_size) {
    const float* x      = (const float*)d_in[0];
    const int*   eidx   = (const int*)d_in[1];     // [2, E]: row then col
    const float* W      = (const float*)d_in[2];
    const float* b      = (const float*)d_in[3];
    const float* gamma  = (const float*)d_in[4];
    const float* beta   = (const float*)d_in[5];
    float* out = (float*)d_out;

    const int* rowIdx = eidx;
    const int* colIdx = eidx + N_EDGES;

    static bool attr_set = false;
    const int gemm_smem = (8192 + 32 * XPAD) * sizeof(float);   // 66048 B
    if (!attr_set) {
        cudaFuncSetAttribute(k_gemm, cudaFuncAttributeMaxDynamicSharedMemorySize, gemm_smem);
        attr_set = true;
    }

    k_init<<<(N_NODES + 255) / 256, 256>>>();
    k_deg<<<(N_EDGES + 255) / 256, 256>>>(colIdx);
    k_dinv<<<(N_NODES + 255) / 256, 256>>>();
    k_blockscan<<<NBLK_SCAN, 256>>>();
    k_scanb<<<1, 512>>>();
    k_offadd<<<NBLK_SCAN, 256>>>();
    k_bin<<<(N_EDGES + 255) / 256, 256>>>(rowIdx, colIdx);
    k_gemm<<<(N_NODES + 255) / 256, 256, gemm_smem>>>(x, W);
    k_agg<<<(N_NODES * 16 + 255) / 256, 256>>>(out);
    k_stats<<<2048, 256>>>(out, b);
    k_fold<<<1, 64>>>(b, gamma, beta);
    k_final<<<(N_NODES * 16 + 255) / 256, 256>>>(out);
}